// round 12
// baseline (speedup 1.0000x reference)
#include <cuda_runtime.h>
#include <cstdint>

#define NHID    512
#define NCLS    250
#define WROWS   200
#define OUTW    450
#define MAXTOK  2048
#define CR      10                    // weight rows per chunk (divides 200 & 250)
#define CHB     (CR * NHID * 4)       // 20480 bytes per chunk
#define NBUF    3
#define SMEM_DYN (NBUF * CHB)         // 61440

extern __shared__ __align__(128) char dynsmem[];

// ---- packed fp32x2 FMA (FFMA2): PTX-only on sm_103a, 2x FFMA throughput ----
__device__ __forceinline__ void fma2(unsigned long long& acc,
                                     unsigned long long a,
                                     unsigned long long b) {
    asm("fma.rn.f32x2 %0, %1, %2, %0;" : "+l"(acc) : "l"(a), "l"(b));
}
__device__ __forceinline__ float2 u2f(unsigned long long v) {
    float2 f;
    asm("mov.b64 {%0, %1}, %2;" : "=f"(f.x), "=f"(f.y) : "l"(v));
    return f;
}
__device__ __forceinline__ uint32_t smem_u32(const void* p) {
    uint32_t a;
    asm("{ .reg .u64 t; cvta.to.shared.u64 t, %1; cvt.u32.u64 %0, t; }"
        : "=r"(a) : "l"(p));
    return a;
}

// ---- mbarrier + bulk-async (TMA-path) primitives ----
__device__ __forceinline__ void mbar_init(uint32_t m, uint32_t cnt) {
    asm volatile("mbarrier.init.shared.b64 [%0], %1;" :: "r"(m), "r"(cnt)
                 : "memory");
}
__device__ __forceinline__ void mbar_expect(uint32_t m, uint32_t bytes) {
    asm volatile("mbarrier.arrive.expect_tx.shared.b64 _, [%0], %1;"
                 :: "r"(m), "r"(bytes) : "memory");
}
__device__ __forceinline__ void bulk_g2s(uint32_t dst, const void* src,
                                         uint32_t bytes, uint32_t m) {
    asm volatile(
        "cp.async.bulk.shared::cta.global.mbarrier::complete_tx::bytes "
        "[%0], [%1], %2, [%3];"
        :: "r"(dst), "l"(src), "r"(bytes), "r"(m) : "memory");
}
__device__ __forceinline__ void mbar_wait(uint32_t m, uint32_t parity) {
    asm volatile(
        "{\n\t.reg .pred P;\n\t"
        "W_%=:\n\t"
        "mbarrier.try_wait.parity.acquire.cta.shared::cta.b64 P, [%0], %1, 0x989680;\n\t"
        "@P bra.uni D_%=;\n\t"
        "bra.uni W_%=;\n\t"
        "D_%=:\n\t}"
        :: "r"(m), "r"(parity) : "memory");
}

// ---- sweep all nrows of W for this warp's 2 register-resident tokens ----
// Lane = (ks = lane>>2, tq = lane&3); lane's k-footprint = 16B units u with
// u%8==ks (interleaved -> warp LDS per step = 128 contiguous bytes, 4-way
// broadcast, conflict-free). Chunks of CR rows arrive via cp.async.bulk into
// a 3-deep mbarrier ring. Returns updated global chunk counter.
__device__ __forceinline__ unsigned sweep(
    const char* W, const float* __restrict__ bias, int nrows, int colbase,
    const ulonglong2* xA, const ulonglong2* xB,   // [16] each, in registers
    int tokA, int tokB, bool vA, bool vB,
    int nsh, int myidx, float* __restrict__ out,
    int tid, int lane, int ks, uint32_t sbase, uint32_t mbar0, unsigned cg) {
    const int nc = nrows / CR;

    if (tid == 0) {
        const int pre = nc < NBUF ? nc : NBUF;
        for (int p = 0; p < pre; p++) {
            const unsigned g = cg + p;
            const uint32_t m = mbar0 + (g % NBUF) * 8;
            mbar_expect(m, CHB);
            bulk_g2s(sbase + (g % NBUF) * CHB, W + (size_t)p * CHB, CHB, m);
        }
    }

    for (int c = 0; c < nc; c++) {
        const unsigned g = cg + c;
        const uint32_t m = mbar0 + (g % NBUF) * 8;
        mbar_wait(m, (g / NBUF) & 1);
        const char* buf = dynsmem + (g % NBUF) * CHB;

        for (int r = myidx; r < CR; r += nsh) {
            const ulonglong2* wrow =
                (const ulonglong2*)(buf + r * (NHID * 4)) + ks;
            unsigned long long a0 = 0, a1 = 0, b0 = 0, b1 = 0;
#pragma unroll
            for (int j = 0; j < 16; j++) {
                ulonglong2 w = wrow[j * 8];       // 128B warp span, broadcast
                fma2(a0, w.x, xA[j].x);
                fma2(a1, w.y, xA[j].y);
                fma2(b0, w.x, xB[j].x);
                fma2(b1, w.y, xB[j].y);
            }
            float2 fa0 = u2f(a0), fa1 = u2f(a1);
            float2 fb0 = u2f(b0), fb1 = u2f(b1);
            float sA = (fa0.x + fa0.y) + (fa1.x + fa1.y);
            float sB = (fb0.x + fb0.y) + (fb1.x + fb1.y);
            sA += __shfl_xor_sync(0xffffffffu, sA, 4);
            sB += __shfl_xor_sync(0xffffffffu, sB, 4);
            sA += __shfl_xor_sync(0xffffffffu, sA, 8);
            sB += __shfl_xor_sync(0xffffffffu, sB, 8);
            sA += __shfl_xor_sync(0xffffffffu, sA, 16);
            sB += __shfl_xor_sync(0xffffffffu, sB, 16);
            if (lane < 4) {
                const int gr = c * CR + r;
                const float bi = __ldg(bias + gr);
                if (vA)
                    out[(size_t)tokA * OUTW + colbase + gr] = sA + bi;
                if (vB)
                    out[(size_t)tokB * OUTW + colbase + gr] = sB + bi;
            }
        }
        __syncthreads();                          // buffer fully consumed
        if (tid == 0 && c + NBUF < nc) {
            const unsigned g2 = g + NBUF;
            const uint32_t m2 = mbar0 + (g2 % NBUF) * 8;
            mbar_expect(m2, CHB);
            bulk_g2s(sbase + (g2 % NBUF) * CHB,
                     W + (size_t)(c + NBUF) * CHB, CHB, m2);
        }
    }
    return cg + nc;
}

__global__ __launch_bounds__(128, 3)
void decoder_kernel(const float* __restrict__ x,
                    const float* __restrict__ Wc,
                    const float* __restrict__ bc,
                    const float* __restrict__ Ww,
                    const float* __restrict__ bw,
                    const int* __restrict__ cls_raw,
                    float* __restrict__ out, int n) {
    __shared__ int s_tok[MAXTOK];
    __shared__ int s_cnt, s_not64;
    __shared__ __align__(8) unsigned long long s_mbar[NBUF];
    const int tid = threadIdx.x;
    const int warp = tid >> 5, lane = tid & 31;
    const int ks = lane >> 2, tq = lane & 3;
    const int bi = blockIdx.x;
    const uint32_t sbase = smem_u32(dynsmem);
    const uint32_t mbar0 = smem_u32(s_mbar);
    const ulonglong2* xg = (const ulonglong2*)x;

    if (tid == 0) {
        for (int b = 0; b < NBUF; b++) mbar_init(mbar0 + b * 8, 1);
        s_cnt = 0;
        s_not64 = 0;
    }
    __syncthreads();

    if (bi < NCLS) {
        // ----------------- words: one class per CTA -----------------
        const int c = bi;
        // int32 vs int64 detection: odd int32 slots of int64 values in
        // [0,250) are all zero; int32 class values are not all zero.
        int flag = 0;
        for (int j = 2 * tid + 1; j < n; j += 256)
            if (cls_raw[j] != 0) flag = 1;
        if (flag) s_not64 = 1;
        __syncthreads();
        const int is64 = !s_not64;
        for (int i = tid; i < n; i += 128) {
            int cc = is64 ? cls_raw[2 * i] : cls_raw[i];
            if (cc == c) {
                int p = atomicAdd(&s_cnt, 1);
                if (p < MAXTOK) s_tok[p] = i;
            }
        }
        __syncthreads();
        const int cnt = min(s_cnt, MAXTOK);
        if (cnt == 0) return;

        const char* Wg = (const char*)Ww + (size_t)c * WROWS * NHID * 4;
        const float* biasw = bw + (size_t)c * WROWS;

        unsigned cg = 0;
        for (int base = 0; base < cnt; base += 32) {
            const int tcnt = min(32, cnt - base);
            int O = (tcnt + 7) >> 3;              // token octets this pass
            if (O == 3) O = 4;                    // keep nsh integral
            const int nsh = 4 / O;
            const int myoct = warp % O;
            const int myidx = warp / O;
            const int tpA = base + myoct * 8 + tq;
            const int tpB = tpA + 4;
            const bool vA = tpA < cnt, vB = tpB < cnt;
            const int tokA = s_tok[vA ? tpA : cnt - 1];
            const int tokB = s_tok[vB ? tpB : cnt - 1];

            ulonglong2 xA[16], xB[16];
#pragma unroll
            for (int j = 0; j < 16; j++) {
                xA[j] = xg[(size_t)tokA * 128 + j * 8 + ks];
                xB[j] = xg[(size_t)tokB * 128 + j * 8 + ks];
            }
            cg = sweep(Wg, biasw, WROWS, NCLS, xA, xB, tokA, tokB, vA, vB,
                       nsh, myidx, out, tid, lane, ks, sbase, mbar0, cg);
        }
    } else {
        // ------------- cls: 32 tokens x all 250 rows per CTA -------------
        const int q = bi - NCLS;
        const int t0 = q * 32;
        if (t0 >= n) return;
        const int tpA = t0 + warp * 8 + tq;
        const int tpB = tpA + 4;
        const bool vA = tpA < n, vB = tpB < n;
        const int tokA = vA ? tpA : n - 1;
        const int tokB = vB ? tpB : n - 1;

        ulonglong2 xA[16], xB[16];
#pragma unroll
        for (int j = 0; j < 16; j++) {
            xA[j] = xg[(size_t)tokA * 128 + j * 8 + ks];
            xB[j] = xg[(size_t)tokB * 128 + j * 8 + ks];
        }
        sweep((const char*)Wc, bc, NCLS, 0, xA, xB, tokA, tokB, vA, vB,
              /*nsh=*/1, /*myidx=*/0, out, tid, lane, ks, sbase, mbar0, 0);
    }
}

extern "C" void kernel_launch(void* const* d_in, const int* in_sizes, int n_in,
                              void* d_out, int out_size) {
    const float* x  = (const float*)d_in[0];
    const float* Wc = (const float*)d_in[1];
    const float* bc = (const float*)d_in[2];
    const float* Ww = (const float*)d_in[3];
    const float* bw = (const float*)d_in[4];
    const int*   ci = (const int*)d_in[5];
    const int n = in_sizes[0] / NHID;
    float* out = (float*)d_out;

    cudaFuncSetAttribute(decoder_kernel,
                         cudaFuncAttributeMaxDynamicSharedMemorySize, SMEM_DYN);
    const int grid = NCLS + (n + 31) / 32;
    decoder_kernel<<<grid, 128, SMEM_DYN>>>(x, Wc, bc, Ww, bw, ci, out, n);
}